// round 15
// baseline (speedup 1.0000x reference)
#include <cuda_runtime.h>
#include <math.h>
#include <stdint.h>

// Problem constants
#define EMBED   256
#define NHEADS  4
#define HDIM    64
#define BATCHB  4
#define SEQ     2048
#define ROWS    (BATCHB*SEQ)
#define BH      (BATCHB*NHEADS)
#define SZ      ((long)ROWS*EMBED)

// ---------------- scratch -----------------------------------------------------
__device__ float g_Bst[512*512];        // stacked FFN B: [W0top ; Wout@W0bot]
__device__ float g_bf [512];            // fused FFN bias
__device__ float g_qkv[4*SZ];           // qk0, qk1 (hd-permuted), v0, v1 (natural)
__device__ float g_m  [2*SZ];           // attention outputs
__device__ float g_y  [2L*ROWS*512];    // FFN hidden

// ---------------- helpers -----------------------------------------------------
__device__ __forceinline__ void mma_tf32(float d[4], const uint32_t a[4], const uint32_t b[2]) {
    asm volatile(
        "mma.sync.aligned.m16n8k8.row.col.f32.tf32.tf32.f32 "
        "{%0,%1,%2,%3},{%4,%5,%6,%7},{%8,%9},{%0,%1,%2,%3};"
        : "+f"(d[0]), "+f"(d[1]), "+f"(d[2]), "+f"(d[3])
        : "r"(a[0]), "r"(a[1]), "r"(a[2]), "r"(a[3]), "r"(b[0]), "r"(b[1]));
}
__device__ __forceinline__ float ex2(float x) {
    float r;
    asm("ex2.approx.f32 %0, %1;" : "=f"(r) : "f"(x));
    return r;
}
__device__ __forceinline__ void cpa16(void* smem, const void* gmem) {
    uint32_t s = (uint32_t)__cvta_generic_to_shared(smem);
    asm volatile("cp.async.cg.shared.global [%0], [%1], 16;" :: "r"(s), "l"(gmem));
}
__device__ __forceinline__ void cp_commit() { asm volatile("cp.async.commit_group;"); }
__device__ __forceinline__ void cp_wait1()  { asm volatile("cp.async.wait_group 1;"); }
__device__ __forceinline__ void cp_wait0()  { asm volatile("cp.async.wait_group 0;"); }

// ---------------- fused FFN bias: bf = b0 + bout @ W0bot ----------------------
__global__ void bias_fuse_kernel(const float* __restrict__ bout,
                                 const float* __restrict__ W0bot,
                                 const float* __restrict__ b0,
                                 float* __restrict__ bf)
{
    int n = blockIdx.x * blockDim.x + threadIdx.x;
    float s = b0[n];
    for (int k = 0; k < 256; k++) s += bout[k] * W0bot[(long)k * 512 + n];
    bf[n] = s;
}

// ---------------- pipelined tensor-core tf32 GEMM -----------------------------
// A and B may be raw fp32 — mma HW truncates both operands to tf32 for free.
// BM=64, BN=128, BK=16, 256 threads (8 warps of 16x64), 3 stages,
// ONE barrier per k-tile.
// PERM: for z<2 (qk outputs), permute output hd columns within each 8-block
// (l<4 -> 2l, else 2(l-4)+1) so flash can use 64-bit fragment loads.
template<int KSPLIT, int PERM>
__global__ __launch_bounds__(256)
void mma_gemm(
    const float* __restrict__ A0, const float* __restrict__ A1,
    const float* __restrict__ A2, long a2Stride,
    const float* __restrict__ B0, const float* __restrict__ B1,
    const float* __restrict__ bias0, const float* __restrict__ bias1,
    const float* __restrict__ res0, const float* __restrict__ res1,
    float* __restrict__ Cb, long cStride,
    int M, int N, int K, int lda, int ldb, int ldc, int ldr)
{
    constexpr int ASTR = 20;
    constexpr int BSTR = 136;
    __shared__ float As[3][64][ASTR];
    __shared__ float Bs[3][16][BSTR];

    const int z = blockIdx.z;
    const float* Aa  = (z & 1) ? A1 : A0;
    const float* Ab  = KSPLIT ? (A2 + (z & 1) * a2Stride) : nullptr;
    const float* B   = (z >> 1) ? B1 : B0;
    const float* bias= (z >> 1) ? bias1 : bias0;
    const float* res = (z & 1) ? res1 : res0;
    float* C = Cb + (long)z * cStride;

    const int tid  = threadIdx.x;
    const int warp = tid >> 5;
    const int lane = tid & 31;
    const int qr = lane >> 2, qc = lane & 3;
    const int rowBase = blockIdx.y * 64;
    const int colBase = blockIdx.x * 128;
    const int wm0 = (warp >> 1) * 16;
    const int wn0 = (warp & 1) * 64;

    float acc[8][4];
    #pragma unroll
    for (int j = 0; j < 8; j++)
        #pragma unroll
        for (int r = 0; r < 4; r++) acc[j][r] = 0.f;

    const int KT = K / 16;
    const int Khalf = K / 2;

    auto loadTile = [&](int st, int kt) {
        int k0 = kt * 16;
        const float* Ac; int kb;
        if (KSPLIT && k0 >= Khalf) { Ac = Ab; kb = k0 - Khalf; }
        else                       { Ac = Aa; kb = k0; }
        #pragma unroll
        for (int i = tid; i < 256; i += 256) {
            int m = i >> 2, kg = i & 3;
            cpa16(&As[st][m][kg * 4], Ac + (long)(rowBase + m) * lda + kb + kg * 4);
        }
        #pragma unroll
        for (int i = tid; i < 512; i += 256) {
            int r = i >> 5, c4 = (i & 31) * 4;
            cpa16(&Bs[st][r][c4], B + (long)(k0 + r) * ldb + colBase + c4);
        }
    };

    loadTile(0, 0); cp_commit();
    loadTile(1, 1); cp_commit();

    for (int kt = 0; kt < KT; kt++) {
        const int st = kt % 3;
        cp_wait1();
        __syncthreads();
        if (kt + 2 < KT) loadTile((kt + 2) % 3, kt + 2);
        cp_commit();

        #pragma unroll
        for (int ks = 0; ks < 16; ks += 8) {
            uint32_t af[4];
            af[0] = __float_as_uint(As[st][wm0 + qr    ][ks + qc]);
            af[1] = __float_as_uint(As[st][wm0 + qr + 8][ks + qc]);
            af[2] = __float_as_uint(As[st][wm0 + qr    ][ks + qc + 4]);
            af[3] = __float_as_uint(As[st][wm0 + qr + 8][ks + qc + 4]);
            #pragma unroll
            for (int nt = 0; nt < 8; nt++) {
                int nr = wn0 + nt * 8;
                uint32_t bf[2] = {
                    __float_as_uint(Bs[st][ks + qc    ][nr + qr]),
                    __float_as_uint(Bs[st][ks + qc + 4][nr + qr]) };
                mma_tf32(acc[nt], af, bf);
            }
        }
    }

    #pragma unroll
    for (int nt = 0; nt < 8; nt++) {
        int gm = rowBase + wm0 + qr;
        int gn = colBase + wn0 + nt * 8 + qc * 2;
        float b0v = bias ? bias[gn] : 0.f;
        float b1v = bias ? bias[gn + 1] : 0.f;
        float v0 = acc[nt][0] + b0v;
        float v1 = acc[nt][1] + b1v;
        float v2 = acc[nt][2] + b0v;
        float v3 = acc[nt][3] + b1v;
        if (res) {
            const float2 r0 = *(const float2*)(res + (long)gm * ldr + gn);
            const float2 r1 = *(const float2*)(res + (long)(gm + 8) * ldr + gn);
            v0 += r0.x; v1 += r0.y; v2 += r1.x; v3 += r1.y;
        }
        if (PERM && (z >> 1) == 0) {
            // permute hd column within its 8-block (qk outputs only)
            int l0  = gn & 7;                    // = 2*qc (even)
            int blk = gn & ~7;
            int p0  = blk + ((l0     < 4) ? 2*l0         : 2*(l0-4)+1);
            int p1  = blk + ((l0 + 1 < 4) ? 2*(l0+1)     : 2*(l0+1-4)+1);
            C[(long)gm * ldc + p0]       = v0;
            C[(long)gm * ldc + p1]       = v1;
            C[(long)(gm + 8) * ldc + p0] = v2;
            C[(long)(gm + 8) * ldc + p1] = v3;
        } else {
            *(float2*)(C + (long)gm * ldc + gn)       = make_float2(v0, v1);
            *(float2*)(C + (long)(gm + 8) * ldc + gn) = make_float2(v2, v3);
        }
    }
}

// ---------------- fused flash cross-attention --------------------------------
// 128 queries per CTA, 4 fat warps (32 rows each = 2 m-tiles).
// qk inputs are hd-PERMUTED (proj epilogue) so each Q/K fragment pair is
// physically adjacent -> single LDS.64. K stride 72 (conflict-free for
// paired loads). No-max softmax; ex2.approx; K+V double-buffered, one
// barrier per iteration.
#define PSTR 68
#define KSTR 72
#define VSTR 72
#define FL_P   0                        // 128 x 68 = 8704 floats
#define FL_K0  8704                     // 2 stages x 64 x 72 = 9216
#define FL_V0  17920                    // 2 stages x 64 x 72 = 9216
#define FL_SMEM ((8704 + 9216 + 9216) * 4)   // 108544 bytes
#define QSCALE 0.18033688011112042f     // 0.125 * log2(e)

__global__ __launch_bounds__(128)
void flash_kernel(const float* __restrict__ qkv, float* __restrict__ mOut)
{
    extern __shared__ float sm[];
    const int z = blockIdx.z;
    const float* Qg = qkv + (long)z * SZ;
    const float* Kg = qkv + (long)(1 - z) * SZ;
    const float* Vg = qkv + (long)(3 - z) * SZ;
    float*       Og = mOut + (long)z * SZ;

    float (*Ps)[PSTR] = (float(*)[PSTR])(sm + FL_P);

    const long base = (long)(blockIdx.y >> 2) * SEQ * EMBED + (blockIdx.y & 3) * HDIM;
    const float* Qp = Qg + base + (long)blockIdx.x * 128 * EMBED;
    const float* K0 = Kg + base;
    const float* V0 = Vg + base;
    float*       Op = Og + base + (long)blockIdx.x * 128 * EMBED;

    const int tid  = threadIdx.x;
    const int warp = tid >> 5;
    const int lane = tid & 31;
    const int qr = lane >> 2, qc = lane & 3;
    const int mr = warp * 32;              // 32 query rows per warp

    auto loadK = [&](int st, int kb) {
        float* Ks = sm + FL_K0 + st * 4608;
        const float* Kp = K0 + (long)kb * 64 * EMBED;
        #pragma unroll
        for (int i = tid; i < 64 * 16; i += 128) {
            int r = i >> 4, c4 = (i & 15) * 4;
            cpa16(Ks + r * KSTR + c4, Kp + (long)r * EMBED + c4);
        }
    };
    auto loadV = [&](int st, int kb) {
        float* Vs = sm + FL_V0 + st * 4608;
        const float* Vp = V0 + (long)kb * 64 * EMBED;
        #pragma unroll
        for (int i = tid; i < 64 * 16; i += 128) {
            int r = i >> 4, c4 = (i & 15) * 4;
            cpa16(Vs + r * VSTR + c4, Vp + (long)r * EMBED + c4);
        }
    };

    // Prologue: group A = {K0,V0}; group B = {K1,V1}
    loadK(0, 0); loadV(0, 0); cp_commit();
    loadK(1, 1); loadV(1, 1); cp_commit();

    // Stage Q (128x64, hd-permuted) pre-scaled to log2 domain while loads fly
    #pragma unroll
    for (int i = tid; i < 128 * 16; i += 128) {
        int r = i >> 4, c4 = (i & 15) * 4;
        float4 v = *(const float4*)(Qp + (long)r * EMBED + c4);
        Ps[r][c4+0] = v.x * QSCALE; Ps[r][c4+1] = v.y * QSCALE;
        Ps[r][c4+2] = v.z * QSCALE; Ps[r][c4+3] = v.w * QSCALE;
    }
    // single prologue barrier: proves Ps(Q) visible AND {K0,V0} complete
    cp_wait1();
    __syncthreads();

    // Q fragments: permuted layout -> logical (qc, qc+4) at physical (2qc, 2qc+1)
    uint32_t qf[2][8][4];
    #pragma unroll
    for (int mt = 0; mt < 2; mt++) {
        const int rb = mr + mt * 16;
        #pragma unroll
        for (int ks = 0; ks < 8; ks++) {
            float2 qa = *(const float2*)&Ps[rb+qr  ][ks*8 + 2*qc];
            float2 qb = *(const float2*)&Ps[rb+qr+8][ks*8 + 2*qc];
            qf[mt][ks][0] = __float_as_uint(qa.x);
            qf[mt][ks][1] = __float_as_uint(qb.x);
            qf[mt][ks][2] = __float_as_uint(qa.y);
            qf[mt][ks][3] = __float_as_uint(qb.y);
        }
    }

    float oacc[2][8][4];
    #pragma unroll
    for (int mt = 0; mt < 2; mt++)
        #pragma unroll
        for (int nt = 0; nt < 8; nt++)
            #pragma unroll
            for (int j = 0; j < 4; j++) oacc[mt][nt][j] = 0.f;
    float lrow[2][2] = {{0.f,0.f},{0.f,0.f}};

    const int NB = SEQ / 64;
    for (int kb = 0; kb < NB; kb++) {
        const int st = kb & 1;
        const float* Ks = sm + FL_K0 + st * 4608;
        const float* Vs = sm + FL_V0 + st * 4608;

        // ---- S = Q K^T; K fragment pair = ONE 64-bit LDS (permuted layout) ----
        float s[2][8][4];
        #pragma unroll
        for (int mt = 0; mt < 2; mt++)
            #pragma unroll
            for (int nt = 0; nt < 8; nt++)
                #pragma unroll
                for (int j = 0; j < 4; j++) s[mt][nt][j] = 0.f;
        #pragma unroll
        for (int ks = 0; ks < 8; ks++) {
            #pragma unroll
            for (int nt = 0; nt < 8; nt++) {
                const float2 kk = *(const float2*)&Ks[(nt*8+qr)*KSTR + ks*8 + 2*qc];
                uint32_t bb[2] = { __float_as_uint(kk.x), __float_as_uint(kk.y) };
                mma_tf32(s[0][nt], qf[0][ks], bb);
                mma_tf32(s[1][nt], qf[1][ks], bb);
            }
        }

        // ---- exp2 (logits already in log2 domain; no max needed) ----
        #pragma unroll
        for (int mt = 0; mt < 2; mt++) {
            float sum0 = 0.f, sum1 = 0.f;
            #pragma unroll
            for (int nt = 0; nt < 8; nt++) {
                s[mt][nt][0] = ex2(s[mt][nt][0]); sum0 += s[mt][nt][0];
                s[mt][nt][1] = ex2(s[mt][nt][1]); sum0 += s[mt][nt][1];
                s[mt][nt][2] = ex2(s[mt][nt][2]); sum1 += s[mt][nt][2];
                s[mt][nt][3] = ex2(s[mt][nt][3]); sum1 += s[mt][nt][3];
            }
            lrow[mt][0] += sum0;
            lrow[mt][1] += sum1;
            // P -> smem (raw fp32; mma truncates); natural key order
            const int rb = mr + mt * 16;
            #pragma unroll
            for (int nt = 0; nt < 8; nt++) {
                Ps[rb+qr  ][nt*8+qc*2  ] = s[mt][nt][0];
                Ps[rb+qr  ][nt*8+qc*2+1] = s[mt][nt][1];
                Ps[rb+qr+8][nt*8+qc*2  ] = s[mt][nt][2];
                Ps[rb+qr+8][nt*8+qc*2+1] = s[mt][nt][3];
            }
        }

        // {K(kb+1),V(kb+1)} ready & visible; barrier also proves all warps
        // finished QK(kb) (frees K[st]) and PV(kb-1) (frees V[st^1]).
        cp_wait0();
        __syncthreads();

        // single combined prefetch group: K(kb+2) -> K[st], V(kb+2) -> V[st]
        if (kb + 2 < NB) { loadK(st, kb + 2); loadV(st, kb + 2); }
        cp_commit();

        // ---- O += P V ; each V fragment feeds 2 MMAs ----
        #pragma unroll
        for (int ks = 0; ks < 8; ks++) {
            uint32_t af[2][4];
            #pragma unroll
            for (int mt = 0; mt < 2; mt++) {
                const int rb = mr + mt * 16;
                af[mt][0] = __float_as_uint(Ps[rb+qr  ][ks*8+qc  ]);
                af[mt][1] = __float_as_uint(Ps[rb+qr+8][ks*8+qc  ]);
                af[mt][2] = __float_as_uint(Ps[rb+qr  ][ks*8+qc+4]);
                af[mt][3] = __float_as_uint(Ps[rb+qr+8][ks*8+qc+4]);
            }
            #pragma unroll
            for (int nt = 0; nt < 8; nt++) {
                uint32_t bb[2] = {
                    __float_as_uint(Vs[(ks*8+qc  )*VSTR + nt*8+qr]),
                    __float_as_uint(Vs[(ks*8+qc+4)*VSTR + nt*8+qr]) };
                mma_tf32(oacc[0][nt], af[0], bb);
                mma_tf32(oacc[1][nt], af[1], bb);
            }
        }
        // no trailing barrier (next stage is the other buffer).
    }

    // Epilogue: finish the row-sum quad reduction once, then normalize.
    #pragma unroll
    for (int mt = 0; mt < 2; mt++) {
        float l0 = lrow[mt][0], l1 = lrow[mt][1];
        l0 += __shfl_xor_sync(0xffffffffu, l0, 1);
        l0 += __shfl_xor_sync(0xffffffffu, l0, 2);
        l1 += __shfl_xor_sync(0xffffffffu, l1, 1);
        l1 += __shfl_xor_sync(0xffffffffu, l1, 2);
        const float inv0 = 1.f / l0, inv1 = 1.f / l1;
        const int rb = mr + mt * 16;
        #pragma unroll
        for (int nt = 0; nt < 8; nt++) {
            int col = nt * 8 + qc * 2;
            *(float2*)(Op + (long)(rb+qr  ) * EMBED + col) =
                make_float2(oacc[mt][nt][0] * inv0, oacc[mt][nt][1] * inv0);
            *(float2*)(Op + (long)(rb+qr+8) * EMBED + col) =
                make_float2(oacc[mt][nt][2] * inv1, oacc[mt][nt][3] * inv1);
        }
    }
}

// ---------------- LayerNorm(512) + exact GELU: warp per row ------------------
__global__ __launch_bounds__(256)
void ln_gelu_kernel(float* __restrict__ y,
                    const float* __restrict__ sc,
                    const float* __restrict__ bi)
{
    const long row  = (long)blockIdx.x * 8 + (threadIdx.x >> 5);
    const int  lane = threadIdx.x & 31;
    float* p = y + row * 512;

    float4 v[4];
    float sum = 0.f, sq = 0.f;
    #pragma unroll
    for (int j = 0; j < 4; j++) {
        v[j] = *(const float4*)(p + j * 128 + lane * 4);
        sum += v[j].x + v[j].y + v[j].z + v[j].w;
        sq  += v[j].x*v[j].x + v[j].y*v[j].y + v[j].z*v[j].z + v[j].w*v[j].w;
    }
    #pragma unroll
    for (int d = 16; d > 0; d >>= 1) {
        sum += __shfl_xor_sync(0xffffffffu, sum, d);
        sq  += __shfl_xor_sync(0xffffffffu, sq,  d);
    }
    const float mean = sum * (1.f / 512.f);
    const float var  = sq * (1.f / 512.f) - mean * mean;
    const float inv  = rsqrtf(var + 1e-5f);

    #pragma unroll
    for (int j = 0; j < 4; j++) {
        const int c = j * 128 + lane * 4;
        const float4 s4 = *(const float4*)(sc + c);
        const float4 b4 = *(const float4*)(bi + c);
        float g;
        g = (v[j].x - mean) * inv * s4.x + b4.x;
        v[j].x = 0.5f * g * (1.f + erff(g * 0.70710678118654752f));
        g = (v[j].y - mean) * inv * s4.y + b4.y;
        v[j].y = 0.5f * g * (1.f + erff(g * 0.70710678118654752f));
        g = (v[j].z - mean) * inv * s4.z + b4.z;
        v[j].z = 0.5f * g * (1.f + erff(g * 0.70710678118654752f));
        g = (v[j].w - mean) * inv * s4.w + b4.w;
        v[j].w = 0.5f * g * (1.f + erff(g * 0.70710678118654752f));
        *(float4*)(p + c) = v[j];
    }
}

// ---------------- host side ---------------------------------------------------
extern "C" void kernel_launch(void* const* d_in, const int* in_sizes, int n_in,
                              void* d_out, int out_size)
{
    const float* x0       = (const float*)d_in[0];
    const float* x1       = (const float*)d_in[1];
    const float* Wqk      = (const float*)d_in[2];
    const float* bqk      = (const float*)d_in[3];
    const float* Wv       = (const float*)d_in[4];
    const float* bv       = (const float*)d_in[5];
    const float* Wout     = (const float*)d_in[6];
    const float* bout     = (const float*)d_in[7];
    const float* W0       = (const float*)d_in[8];
    const float* b0       = (const float*)d_in[9];
    const float* ln_scale = (const float*)d_in[10];
    const float* ln_bias  = (const float*)d_in[11];
    const float* W3       = (const float*)d_in[12];
    const float* b3       = (const float*)d_in[13];
    float* out = (float*)d_out;

    float *Bst, *bf, *qkv, *m, *y;
    cudaGetSymbolAddress((void**)&Bst, g_Bst);
    cudaGetSymbolAddress((void**)&bf,  g_bf);
    cudaGetSymbolAddress((void**)&qkv, g_qkv);
    cudaGetSymbolAddress((void**)&m,   g_m);
    cudaGetSymbolAddress((void**)&y,   g_y);

    cudaFuncSetAttribute(flash_kernel,
                         cudaFuncAttributeMaxDynamicSharedMemorySize, FL_SMEM);

    // 0) Bst rows 0..255 = W0top (plain D2D copy)
    cudaMemcpyAsync(Bst, W0, 256 * 512 * sizeof(float), cudaMemcpyDeviceToDevice);
    // 0b) Bst rows 256..511 = Wout @ W0bot ; fused bias
    mma_gemm<0,0><<<dim3(4, 4, 1), 256>>>(
        Wout, nullptr, nullptr, 0, W0 + 256*512, nullptr,
        nullptr, nullptr, nullptr, nullptr,
        Bst + 256*512, 0, 256, 512, 256, 256, 512, 512, 0);
    bias_fuse_kernel<<<2, 256>>>(bout, W0 + 256*512, b0, bf);

    // 1) projections: z {0:x0@Wqk, 1:x1@Wqk, 2:x0@Wv, 3:x1@Wv} -> g_qkv[z]
    //    qk outputs (z<2) are written hd-PERMUTED for flash's LDS.64 frags.
    mma_gemm<0,1><<<dim3(2, 128, 4), 256>>>(
        x0, x1, nullptr, 0, Wqk, Wv, bqk, bv, nullptr, nullptr,
        qkv, SZ, ROWS, EMBED, EMBED, EMBED, EMBED, EMBED, 0);

    // 2) flash cross-attention, both directions (128-query fat-warp CTAs)
    flash_kernel<<<dim3(SEQ/128, BH, 2), 128, FL_SMEM>>>(qkv, m);

    // 3) y_z = x_z @ W0top + m_z @ Wfused + bfused   (split-A, stacked B)
    mma_gemm<1,0><<<dim3(4, 128, 2), 256>>>(
        x0, x1, m, SZ, Bst, Bst, bf, bf, nullptr, nullptr,
        y, (long)ROWS * 512, ROWS, 512, 512, EMBED, 512, 512, 0);

    // 4) LayerNorm + GELU in place (warp per row)
    ln_gelu_kernel<<<2 * ROWS / 8, 256>>>(y, ln_scale, ln_bias);

    // 5) out_z = x_z + y_z @ W3 + b3
    mma_gemm<0,0><<<dim3(2, 128, 2), 256>>>(
        y, y + (long)ROWS * 512, nullptr, 0, W3, W3, b3, b3, x0, x1,
        out, SZ, ROWS, EMBED, 512, 512, EMBED, EMBED, EMBED);
}

// round 16
// speedup vs baseline: 1.0315x; 1.0315x over previous
#include <cuda_runtime.h>
#include <math.h>
#include <stdint.h>

// Problem constants
#define EMBED   256
#define NHEADS  4
#define HDIM    64
#define BATCHB  4
#define SEQ     2048
#define ROWS    (BATCHB*SEQ)
#define BH      (BATCHB*NHEADS)
#define SZ      ((long)ROWS*EMBED)

// ---------------- scratch -----------------------------------------------------
__device__ float g_Bst[512*512];        // stacked FFN B: [W0top ; Wout@W0bot]
__device__ float g_bf [512];            // fused FFN bias
__device__ float g_qkv[4*SZ];           // qk0, qk1, v0, v1 (natural layout)
__device__ float g_m  [2*SZ];           // attention outputs
__device__ float g_y  [2L*ROWS*512];    // FFN hidden

// ---------------- helpers -----------------------------------------------------
__device__ __forceinline__ void mma_tf32(float d[4], const uint32_t a[4], const uint32_t b[2]) {
    asm volatile(
        "mma.sync.aligned.m16n8k8.row.col.f32.tf32.tf32.f32 "
        "{%0,%1,%2,%3},{%4,%5,%6,%7},{%8,%9},{%0,%1,%2,%3};"
        : "+f"(d[0]), "+f"(d[1]), "+f"(d[2]), "+f"(d[3])
        : "r"(a[0]), "r"(a[1]), "r"(a[2]), "r"(a[3]), "r"(b[0]), "r"(b[1]));
}
__device__ __forceinline__ float ex2(float x) {
    float r;
    asm("ex2.approx.f32 %0, %1;" : "=f"(r) : "f"(x));
    return r;
}
__device__ __forceinline__ void cpa16(void* smem, const void* gmem) {
    uint32_t s = (uint32_t)__cvta_generic_to_shared(smem);
    asm volatile("cp.async.cg.shared.global [%0], [%1], 16;" :: "r"(s), "l"(gmem));
}
__device__ __forceinline__ void cp_commit() { asm volatile("cp.async.commit_group;"); }
__device__ __forceinline__ void cp_wait1()  { asm volatile("cp.async.wait_group 1;"); }
__device__ __forceinline__ void cp_wait0()  { asm volatile("cp.async.wait_group 0;"); }

// ---------------- fused FFN bias: bf = b0 + bout @ W0bot ----------------------
__global__ void bias_fuse_kernel(const float* __restrict__ bout,
                                 const float* __restrict__ W0bot,
                                 const float* __restrict__ b0,
                                 float* __restrict__ bf)
{
    int n = blockIdx.x * blockDim.x + threadIdx.x;
    float s = b0[n];
    for (int k = 0; k < 256; k++) s += bout[k] * W0bot[(long)k * 512 + n];
    bf[n] = s;
}

// ---------------- pipelined tensor-core tf32 GEMM -----------------------------
// A and B may be raw fp32 — mma HW truncates both operands to tf32 for free.
// BM=64, BN=128, BK=16, 256 threads (8 warps of 16x64), 3 stages,
// ONE barrier per k-tile.
template<int KSPLIT>
__global__ __launch_bounds__(256)
void mma_gemm(
    const float* __restrict__ A0, const float* __restrict__ A1,
    const float* __restrict__ A2, long a2Stride,
    const float* __restrict__ B0, const float* __restrict__ B1,
    const float* __restrict__ bias0, const float* __restrict__ bias1,
    const float* __restrict__ res0, const float* __restrict__ res1,
    float* __restrict__ Cb, long cStride,
    int M, int N, int K, int lda, int ldb, int ldc, int ldr)
{
    constexpr int ASTR = 20;
    constexpr int BSTR = 136;
    __shared__ float As[3][64][ASTR];
    __shared__ float Bs[3][16][BSTR];

    const int z = blockIdx.z;
    const float* Aa  = (z & 1) ? A1 : A0;
    const float* Ab  = KSPLIT ? (A2 + (z & 1) * a2Stride) : nullptr;
    const float* B   = (z >> 1) ? B1 : B0;
    const float* bias= (z >> 1) ? bias1 : bias0;
    const float* res = (z & 1) ? res1 : res0;
    float* C = Cb + (long)z * cStride;

    const int tid  = threadIdx.x;
    const int warp = tid >> 5;
    const int lane = tid & 31;
    const int qr = lane >> 2, qc = lane & 3;
    const int rowBase = blockIdx.y * 64;
    const int colBase = blockIdx.x * 128;
    const int wm0 = (warp >> 1) * 16;   // 4 warp-rows x 16
    const int wn0 = (warp & 1) * 64;    // 2 warp-cols x 64

    float acc[8][4];
    #pragma unroll
    for (int j = 0; j < 8; j++)
        #pragma unroll
        for (int r = 0; r < 4; r++) acc[j][r] = 0.f;

    const int KT = K / 16;
    const int Khalf = K / 2;

    auto loadTile = [&](int st, int kt) {
        int k0 = kt * 16;
        const float* Ac; int kb;
        if (KSPLIT && k0 >= Khalf) { Ac = Ab; kb = k0 - Khalf; }
        else                       { Ac = Aa; kb = k0; }
        #pragma unroll
        for (int i = tid; i < 256; i += 256) {
            int m = i >> 2, kg = i & 3;
            cpa16(&As[st][m][kg * 4], Ac + (long)(rowBase + m) * lda + kb + kg * 4);
        }
        #pragma unroll
        for (int i = tid; i < 512; i += 256) {
            int r = i >> 5, c4 = (i & 31) * 4;
            cpa16(&Bs[st][r][c4], B + (long)(k0 + r) * ldb + colBase + c4);
        }
    };

    // prologue: tiles 0 and 1 in flight (one group each)
    loadTile(0, 0); cp_commit();
    loadTile(1, 1); cp_commit();

    for (int kt = 0; kt < KT; kt++) {
        const int st = kt % 3;
        cp_wait1();
        __syncthreads();   // tile kt visible; stage (kt+2)%3 freed by barrier
        if (kt + 2 < KT) loadTile((kt + 2) % 3, kt + 2);
        cp_commit();

        #pragma unroll
        for (int ks = 0; ks < 16; ks += 8) {
            uint32_t af[4];
            af[0] = __float_as_uint(As[st][wm0 + qr    ][ks + qc]);
            af[1] = __float_as_uint(As[st][wm0 + qr + 8][ks + qc]);
            af[2] = __float_as_uint(As[st][wm0 + qr    ][ks + qc + 4]);
            af[3] = __float_as_uint(As[st][wm0 + qr + 8][ks + qc + 4]);
            #pragma unroll
            for (int nt = 0; nt < 8; nt++) {
                int nr = wn0 + nt * 8;
                uint32_t bf[2] = {
                    __float_as_uint(Bs[st][ks + qc    ][nr + qr]),
                    __float_as_uint(Bs[st][ks + qc + 4][nr + qr]) };
                mma_tf32(acc[nt], af, bf);
            }
        }
    }

    #pragma unroll
    for (int nt = 0; nt < 8; nt++) {
        int gm = rowBase + wm0 + qr;
        int gn = colBase + wn0 + nt * 8 + qc * 2;
        float b0v = bias ? bias[gn] : 0.f;
        float b1v = bias ? bias[gn + 1] : 0.f;
        float v0 = acc[nt][0] + b0v;
        float v1 = acc[nt][1] + b1v;
        float v2 = acc[nt][2] + b0v;
        float v3 = acc[nt][3] + b1v;
        if (res) {
            const float2 r0 = *(const float2*)(res + (long)gm * ldr + gn);
            const float2 r1 = *(const float2*)(res + (long)(gm + 8) * ldr + gn);
            v0 += r0.x; v1 += r0.y; v2 += r1.x; v3 += r1.y;
        }
        *(float2*)(C + (long)gm * ldc + gn)       = make_float2(v0, v1);
        *(float2*)(C + (long)(gm + 8) * ldc + gn) = make_float2(v2, v3);
    }
}

// ---------------- fused flash cross-attention --------------------------------
// 128 queries per CTA, 4 fat warps (32 rows each = 2 m-tiles).
// No-max softmax (logits O(0.1)); Q pre-scaled by 0.125*log2e -> ex2.approx.
// K AND V double-buffered -> ONE barrier per iteration.
// B-fragment loads register-double-buffered (load nt+1 before MMAs of nt).
#define KSTR 68
#define VSTR 72
#define FL_P   0                       // 128 x 68 = 8704 floats
#define FL_K0  8704                    // 2 stages x 64 x 68
#define FL_V0  17408                   // 2 stages x 64 x 72
#define FL_SMEM ((17408 + 2*4608) * 4) // 106496 bytes
#define QSCALE 0.18033688011112042f    // 0.125 * log2(e)

__global__ __launch_bounds__(128)
void flash_kernel(const float* __restrict__ qkv, float* __restrict__ mOut)
{
    extern __shared__ float sm[];
    const int z = blockIdx.z;
    const float* Qg = qkv + (long)z * SZ;
    const float* Kg = qkv + (long)(1 - z) * SZ;
    const float* Vg = qkv + (long)(3 - z) * SZ;
    float*       Og = mOut + (long)z * SZ;

    float (*Ps)[KSTR] = (float(*)[KSTR])(sm + FL_P);

    const long base = (long)(blockIdx.y >> 2) * SEQ * EMBED + (blockIdx.y & 3) * HDIM;
    const float* Qp = Qg + base + (long)blockIdx.x * 128 * EMBED;
    const float* K0 = Kg + base;
    const float* V0 = Vg + base;
    float*       Op = Og + base + (long)blockIdx.x * 128 * EMBED;

    const int tid  = threadIdx.x;
    const int warp = tid >> 5;
    const int lane = tid & 31;
    const int qr = lane >> 2, qc = lane & 3;
    const int mr = warp * 32;              // 32 query rows per warp

    auto loadK = [&](int st, int kb) {
        float* Ks = sm + FL_K0 + st * 4352;
        const float* Kp = K0 + (long)kb * 64 * EMBED;
        #pragma unroll
        for (int i = tid; i < 64 * 16; i += 128) {
            int r = i >> 4, c4 = (i & 15) * 4;
            cpa16(Ks + r * KSTR + c4, Kp + (long)r * EMBED + c4);
        }
    };
    auto loadV = [&](int st, int kb) {
        float* Vs = sm + FL_V0 + st * 4608;
        const float* Vp = V0 + (long)kb * 64 * EMBED;
        #pragma unroll
        for (int i = tid; i < 64 * 16; i += 128) {
            int r = i >> 4, c4 = (i & 15) * 4;
            cpa16(Vs + r * VSTR + c4, Vp + (long)r * EMBED + c4);
        }
    };

    // Prologue: group A = {K0,V0}; group B = {K1,V1}
    loadK(0, 0); loadV(0, 0); cp_commit();
    loadK(1, 1); loadV(1, 1); cp_commit();

    // Stage Q (128x64) pre-scaled to log2 domain while loads fly
    #pragma unroll
    for (int i = tid; i < 128 * 16; i += 128) {
        int r = i >> 4, c4 = (i & 15) * 4;
        float4 v = *(const float4*)(Qp + (long)r * EMBED + c4);
        Ps[r][c4+0] = v.x * QSCALE; Ps[r][c4+1] = v.y * QSCALE;
        Ps[r][c4+2] = v.z * QSCALE; Ps[r][c4+3] = v.w * QSCALE;
    }
    // single prologue barrier: proves Ps(Q) visible AND {K0,V0} complete
    cp_wait1();
    __syncthreads();

    uint32_t qf[2][8][4];
    #pragma unroll
    for (int mt = 0; mt < 2; mt++) {
        const int rb = mr + mt * 16;
        #pragma unroll
        for (int ks = 0; ks < 8; ks++) {
            qf[mt][ks][0] = __float_as_uint(Ps[rb+qr  ][ks*8+qc  ]);
            qf[mt][ks][1] = __float_as_uint(Ps[rb+qr+8][ks*8+qc  ]);
            qf[mt][ks][2] = __float_as_uint(Ps[rb+qr  ][ks*8+qc+4]);
            qf[mt][ks][3] = __float_as_uint(Ps[rb+qr+8][ks*8+qc+4]);
        }
    }

    float oacc[2][8][4];
    #pragma unroll
    for (int mt = 0; mt < 2; mt++)
        #pragma unroll
        for (int nt = 0; nt < 8; nt++)
            #pragma unroll
            for (int j = 0; j < 4; j++) oacc[mt][nt][j] = 0.f;
    // per-thread partial row sums of exp (reduced across quad at the end)
    float lrow[2][2] = {{0.f,0.f},{0.f,0.f}};

    const int NB = SEQ / 64;
    for (int kb = 0; kb < NB; kb++) {
        const int st = kb & 1;
        const float* Ks = sm + FL_K0 + st * 4352;
        const float* Vs = sm + FL_V0 + st * 4608;

        // ---- S = Q K^T; K fragments register-double-buffered ----
        float s[2][8][4];
        #pragma unroll
        for (int mt = 0; mt < 2; mt++)
            #pragma unroll
            for (int nt = 0; nt < 8; nt++)
                #pragma unroll
                for (int j = 0; j < 4; j++) s[mt][nt][j] = 0.f;
        #pragma unroll
        for (int ks = 0; ks < 8; ks++) {
            uint32_t bb[2] = {
                __float_as_uint(Ks[qr*KSTR + ks*8+qc    ]),
                __float_as_uint(Ks[qr*KSTR + ks*8+qc + 4]) };
            #pragma unroll
            for (int nt = 0; nt < 8; nt++) {
                uint32_t bn[2];
                if (nt < 7) {
                    bn[0] = __float_as_uint(Ks[((nt+1)*8+qr)*KSTR + ks*8+qc    ]);
                    bn[1] = __float_as_uint(Ks[((nt+1)*8+qr)*KSTR + ks*8+qc + 4]);
                }
                mma_tf32(s[0][nt], qf[0][ks], bb);
                mma_tf32(s[1][nt], qf[1][ks], bb);
                if (nt < 7) { bb[0] = bn[0]; bb[1] = bn[1]; }
            }
        }

        // ---- exp2 (logits already in log2 domain; no max needed) ----
        #pragma unroll
        for (int mt = 0; mt < 2; mt++) {
            float sum0 = 0.f, sum1 = 0.f;
            #pragma unroll
            for (int nt = 0; nt < 8; nt++) {
                s[mt][nt][0] = ex2(s[mt][nt][0]); sum0 += s[mt][nt][0];
                s[mt][nt][1] = ex2(s[mt][nt][1]); sum0 += s[mt][nt][1];
                s[mt][nt][2] = ex2(s[mt][nt][2]); sum1 += s[mt][nt][2];
                s[mt][nt][3] = ex2(s[mt][nt][3]); sum1 += s[mt][nt][3];
            }
            lrow[mt][0] += sum0;
            lrow[mt][1] += sum1;
            // P -> smem (raw fp32; mma truncates)
            const int rb = mr + mt * 16;
            #pragma unroll
            for (int nt = 0; nt < 8; nt++) {
                Ps[rb+qr  ][nt*8+qc*2  ] = s[mt][nt][0];
                Ps[rb+qr  ][nt*8+qc*2+1] = s[mt][nt][1];
                Ps[rb+qr+8][nt*8+qc*2  ] = s[mt][nt][2];
                Ps[rb+qr+8][nt*8+qc*2+1] = s[mt][nt][3];
            }
        }

        // {K(kb+1),V(kb+1)} ready & visible; barrier also proves all warps
        // finished QK(kb) (frees K[st]) and PV(kb-1) (frees V[st^1]).
        cp_wait0();
        __syncthreads();

        // single combined prefetch group: K(kb+2) -> K[st], V(kb+2) -> V[st]
        if (kb + 2 < NB) { loadK(st, kb + 2); loadV(st, kb + 2); }
        cp_commit();

        // ---- O += P V ; V fragments register-double-buffered ----
        #pragma unroll
        for (int ks = 0; ks < 8; ks++) {
            uint32_t af[2][4];
            #pragma unroll
            for (int mt = 0; mt < 2; mt++) {
                const int rb = mr + mt * 16;
                af[mt][0] = __float_as_uint(Ps[rb+qr  ][ks*8+qc  ]);
                af[mt][1] = __float_as_uint(Ps[rb+qr+8][ks*8+qc  ]);
                af[mt][2] = __float_as_uint(Ps[rb+qr  ][ks*8+qc+4]);
                af[mt][3] = __float_as_uint(Ps[rb+qr+8][ks*8+qc+4]);
            }
            uint32_t bb[2] = {
                __float_as_uint(Vs[(ks*8+qc  )*VSTR + qr]),
                __float_as_uint(Vs[(ks*8+qc+4)*VSTR + qr]) };
            #pragma unroll
            for (int nt = 0; nt < 8; nt++) {
                uint32_t bn[2];
                if (nt < 7) {
                    bn[0] = __float_as_uint(Vs[(ks*8+qc  )*VSTR + (nt+1)*8+qr]);
                    bn[1] = __float_as_uint(Vs[(ks*8+qc+4)*VSTR + (nt+1)*8+qr]);
                }
                mma_tf32(oacc[0][nt], af[0], bb);
                mma_tf32(oacc[1][nt], af[1], bb);
                if (nt < 7) { bb[0] = bn[0]; bb[1] = bn[1]; }
            }
        }
        // no trailing barrier (next stage is the other buffer).
    }

    // Epilogue: finish the row-sum quad reduction once, then normalize.
    #pragma unroll
    for (int mt = 0; mt < 2; mt++) {
        float l0 = lrow[mt][0], l1 = lrow[mt][1];
        l0 += __shfl_xor_sync(0xffffffffu, l0, 1);
        l0 += __shfl_xor_sync(0xffffffffu, l0, 2);
        l1 += __shfl_xor_sync(0xffffffffu, l1, 1);
        l1 += __shfl_xor_sync(0xffffffffu, l1, 2);
        const float inv0 = 1.f / l0, inv1 = 1.f / l1;
        const int rb = mr + mt * 16;
        #pragma unroll
        for (int nt = 0; nt < 8; nt++) {
            int col = nt * 8 + qc * 2;
            *(float2*)(Op + (long)(rb+qr  ) * EMBED + col) =
                make_float2(oacc[mt][nt][0] * inv0, oacc[mt][nt][1] * inv0);
            *(float2*)(Op + (long)(rb+qr+8) * EMBED + col) =
                make_float2(oacc[mt][nt][2] * inv1, oacc[mt][nt][3] * inv1);
        }
    }
}

// ---------------- LayerNorm(512) + exact GELU: warp per row ------------------
__global__ __launch_bounds__(256)
void ln_gelu_kernel(float* __restrict__ y,
                    const float* __restrict__ sc,
                    const float* __restrict__ bi)
{
    const long row  = (long)blockIdx.x * 8 + (threadIdx.x >> 5);
    const int  lane = threadIdx.x & 31;
    float* p = y + row * 512;

    float4 v[4];
    float sum = 0.f, sq = 0.f;
    #pragma unroll
    for (int j = 0; j < 4; j++) {
        v[j] = *(const float4*)(p + j * 128 + lane * 4);
        sum += v[j].x + v[j].y + v[j].z + v[j].w;
        sq  += v[j].x*v[j].x + v[j].y*v[j].y + v[j].z*v[j].z + v[j].w*v[j].w;
    }
    #pragma unroll
    for (int d = 16; d > 0; d >>= 1) {
        sum += __shfl_xor_sync(0xffffffffu, sum, d);
        sq  += __shfl_xor_sync(0xffffffffu, sq,  d);
    }
    const float mean = sum * (1.f / 512.f);
    const float var  = sq * (1.f / 512.f) - mean * mean;
    const float inv  = rsqrtf(var + 1e-5f);

    #pragma unroll
    for (int j = 0; j < 4; j++) {
        const int c = j * 128 + lane * 4;
        const float4 s4 = *(const float4*)(sc + c);
        const float4 b4 = *(const float4*)(bi + c);
        float g;
        g = (v[j].x - mean) * inv * s4.x + b4.x;
        v[j].x = 0.5f * g * (1.f + erff(g * 0.70710678118654752f));
        g = (v[j].y - mean) * inv * s4.y + b4.y;
        v[j].y = 0.5f * g * (1.f + erff(g * 0.70710678118654752f));
        g = (v[j].z - mean) * inv * s4.z + b4.z;
        v[j].z = 0.5f * g * (1.f + erff(g * 0.70710678118654752f));
        g = (v[j].w - mean) * inv * s4.w + b4.w;
        v[j].w = 0.5f * g * (1.f + erff(g * 0.70710678118654752f));
        *(float4*)(p + c) = v[j];
    }
}

// ---------------- host side ---------------------------------------------------
extern "C" void kernel_launch(void* const* d_in, const int* in_sizes, int n_in,
                              void* d_out, int out_size)
{
    const float* x0       = (const float*)d_in[0];
    const float* x1       = (const float*)d_in[1];
    const float* Wqk      = (const float*)d_in[2];
    const float* bqk      = (const float*)d_in[3];
    const float* Wv       = (const float*)d_in[4];
    const float* bv       = (const float*)d_in[5];
    const float* Wout     = (const float*)d_in[6];
    const float* bout     = (const float*)d_in[7];
    const float* W0       = (const float*)d_in[8];
    const float* b0       = (const float*)d_in[9];
    const float* ln_scale = (const float*)d_in[10];
    const float* ln_bias  = (const float*)d_in[11];
    const float* W3       = (const float*)d_in[12];
    const float* b3       = (const float*)d_in[13];
    float* out = (float*)d_out;

    float *Bst, *bf, *qkv, *m, *y;
    cudaGetSymbolAddress((void**)&Bst, g_Bst);
    cudaGetSymbolAddress((void**)&bf,  g_bf);
    cudaGetSymbolAddress((void**)&qkv, g_qkv);
    cudaGetSymbolAddress((void**)&m,   g_m);
    cudaGetSymbolAddress((void**)&y,   g_y);

    cudaFuncSetAttribute(flash_kernel,
                         cudaFuncAttributeMaxDynamicSharedMemorySize, FL_SMEM);

    // 0) Bst rows 0..255 = W0top (plain D2D copy)
    cudaMemcpyAsync(Bst, W0, 256 * 512 * sizeof(float), cudaMemcpyDeviceToDevice);
    // 0b) Bst rows 256..511 = Wout @ W0bot ; fused bias
    mma_gemm<0><<<dim3(4, 4, 1), 256>>>(
        Wout, nullptr, nullptr, 0, W0 + 256*512, nullptr,
        nullptr, nullptr, nullptr, nullptr,
        Bst + 256*512, 0, 256, 512, 256, 256, 512, 512, 0);
    bias_fuse_kernel<<<2, 256>>>(bout, W0 + 256*512, b0, bf);

    // 1) projections: z {0:x0@Wqk, 1:x1@Wqk, 2:x0@Wv, 3:x1@Wv} -> g_qkv[z]
    mma_gemm<0><<<dim3(2, 128, 4), 256>>>(
        x0, x1, nullptr, 0, Wqk, Wv, bqk, bv, nullptr, nullptr,
        qkv, SZ, ROWS, EMBED, EMBED, EMBED, EMBED, EMBED, 0);

    // 2) flash cross-attention, both directions (128-query fat-warp CTAs)
    flash_kernel<<<dim3(SEQ/128, BH, 2), 128, FL_SMEM>>>(qkv, m);

    // 3) y_z = x_z @ W0top + m_z @ Wfused + bfused   (split-A, stacked B)
    mma_gemm<1><<<dim3(4, 128, 2), 256>>>(
        x0, x1, m, SZ, Bst, Bst, bf, bf, nullptr, nullptr,
        y, (long)ROWS * 512, ROWS, 512, 512, EMBED, 512, 512, 0);

    // 4) LayerNorm + GELU in place (warp per row)
    ln_gelu_kernel<<<2 * ROWS / 8, 256>>>(y, ln_scale, ln_bias);

    // 5) out_z = x_z + y_z @ W3 + b3
    mma_gemm<0><<<dim3(2, 128, 2), 256>>>(
        y, y + (long)ROWS * 512, nullptr, 0, W3, W3, b3, b3, x0, x1,
        out, SZ, ROWS, EMBED, 512, 512, EMBED, EMBED, EMBED);
}